// round 13
// baseline (speedup 1.0000x reference)
#include <cuda_runtime.h>
#include <cstdint>

#define NN 5000
#define BT 128
#define HR 64            // rows per half-slot
#define HPD 132          // half row stride (floats), conflict-free
#define SPD 132          // S row stride
#define NPAD 5120
#define NTHREADS 512
#define NMAT 12
#define NSLOT 6
#define SLOTF (HR * HPD) // floats per half-slot

__device__ float g_St[2][16][NPAD];   // transposed supports; pad rows zero

// ---------------- helpers ----------------
__device__ __forceinline__ uint32_t f2tf32(float x) {
    uint32_t r;
    asm("cvt.rna.tf32.f32 %0, %1;" : "=r"(r) : "f"(x));
    return r;
}
__device__ __forceinline__ void mma_tf32(float* d, uint32_t a0, uint32_t a1,
                                         uint32_t a2, uint32_t a3,
                                         uint32_t b0, uint32_t b1) {
    asm volatile(
        "mma.sync.aligned.m16n8k8.row.col.f32.tf32.tf32.f32 "
        "{%0,%1,%2,%3}, {%4,%5,%6,%7}, {%8,%9}, {%0,%1,%2,%3};"
        : "+f"(d[0]), "+f"(d[1]), "+f"(d[2]), "+f"(d[3])
        : "r"(a0), "r"(a1), "r"(a2), "r"(a3), "r"(b0), "r"(b1));
}
__device__ __forceinline__ void red_add_v2(float* p, float x, float y) {
    asm volatile("red.global.add.v2.f32 [%0], {%1, %2};"
                 :: "l"(p), "f"(x), "f"(y) : "memory");
}
__device__ __forceinline__ void mbar_init(uint32_t mbar, uint32_t cnt) {
    asm volatile("mbarrier.init.shared.b64 [%0], %1;"
                 :: "r"(mbar), "r"(cnt) : "memory");
}
__device__ __forceinline__ void mbar_expect_tx(uint32_t mbar, uint32_t bytes) {
    asm volatile("mbarrier.arrive.expect_tx.shared.b64 _, [%0], %1;"
                 :: "r"(mbar), "r"(bytes) : "memory");
}
__device__ __forceinline__ void bulk_g2s(uint32_t dst, const void* src,
                                         uint32_t bytes, uint32_t mbar) {
    asm volatile(
        "cp.async.bulk.shared::cta.global.mbarrier::complete_tx::bytes "
        "[%0], [%1], %2, [%3];"
        :: "r"(dst), "l"(src), "r"(bytes), "r"(mbar) : "memory");
}
__device__ __forceinline__ void mbar_wait(uint32_t mbar, uint32_t parity) {
    uint32_t done;
    asm volatile(
        "{\n\t.reg .pred p;\n\t"
        "mbarrier.try_wait.parity.acquire.cta.shared::cta.b64 p, [%1], %2;\n\t"
        "selp.b32 %0, 1, 0, p;\n\t}"
        : "=r"(done) : "r"(mbar), "r"(parity) : "memory");
    if (!done) {
        asm volatile(
            "{\n\t.reg .pred P1;\n\t"
            "WAIT_LOOP_%=:\n\t"
            "mbarrier.try_wait.parity.acquire.cta.shared::cta.b64 P1, [%0], %1, 0x989680;\n\t"
            "@P1 bra.uni WAIT_DONE_%=;\n\t"
            "bra.uni WAIT_LOOP_%=;\n\t"
            "WAIT_DONE_%=:\n\t}"
            :: "r"(mbar), "r"(parity) : "memory");
    }
}

// ---------------- prep: g_St = (feature @ W)^T, bias-init out ----------------
__global__ void fame_prep(const float* __restrict__ feature,
                          const float* __restrict__ W3, const float* __restrict__ b3,
                          const float* __restrict__ W1, const float* __restrict__ b1,
                          float* __restrict__ out) {
    __shared__ float fsm[128];
    const int row = blockIdx.x;
    const int t = threadIdx.x;
    fsm[t] = feature[row * 128 + t];
    __syncthreads();
    if (t < 32) {
        const int g = t >> 4;
        const int c = t & 15;
        const float* __restrict__ W = g ? W1 : W3;
        float s = 0.f;
#pragma unroll 16
        for (int k = 0; k < 128; k++) s += fsm[k] * W[k * 16 + c];
        g_St[g][c][row] = s;
    } else if (t < 64) {
        const int c = t - 32;
        out[row * 32 + c] = (c < 16) ? b3[c] : b1[c - 16];
    }
}

// ---- main: 6-half-slot bulk ring, staggered matrix order, reg-B TF32 mma ----
__global__ __launch_bounds__(NTHREADS, 1)
void fame_main(const float* __restrict__ A, const float* __restrict__ At,
               const float* __restrict__ wA, const float* __restrict__ wB,
               float* __restrict__ out)
{
    extern __shared__ float smem[];
    float* S1u = smem + NSLOT * SLOTF;       // [16][132] tf32 S^T rows j0..
    float* S2u = S1u + 16 * SPD;             // [16][132] tf32 S^T rows i0..
    const uint32_t smem_base = (uint32_t)__cvta_generic_to_shared(smem);
    const uint32_t mbar0 = smem_base + (uint32_t)(NSLOT * SLOTF + 2 * 16 * SPD) * 4u;

    const int t = threadIdx.x;
    const int wid = t >> 5, lane = t & 31;
    const int p = lane >> 2, q = lane & 3;
    const int side = wid >> 3;               // 0: direct GEMM, 1: transpose GEMM
    const int wsub = wid & 7;                // 16-row slice within side
    const int myhalf = wsub >> 2;            // side0 only: which 64-row half I consume
    const int i0 = blockIdx.y * BT, j0 = blockIdx.x * BT;
    const bool interior = (i0 + BT <= NN) && (j0 + BT <= NN);

    // per-CTA matrix-order stagger (matrices within a group commute)
    const int cta = blockIdx.y * gridDim.x + blockIdx.x;
    const int rotA = cta % 3, rotB = cta % 9;
    auto matid = [&](int step) {
        return (step < 3) ? (step + rotA) % 3 : 3 + ((step - 3) + rotB) % 9;
    };

    // ---- prologue: mbarriers + (edge only) zero-fill ring slots ----
    if (t < NSLOT) mbar_init(mbar0 + 8u * (uint32_t)t, (uint32_t)HR);
    if (!interior) {
        for (int idx = t; idx < NSLOT * SLOTF; idx += NTHREADS) smem[idx] = 0.f;
    }
    __syncthreads();

    const uint32_t row_bytes = (uint32_t)((j0 + BT <= NN ? BT : (NN - j0)) * 4);
    // ---- bulk-copy half h of step's matrix into slot (2step+h)%6 ----
    auto issue_half = [&](int step, int h) {
        if (t < HR) {
            const int mm = matid(step);
            const float* __restrict__ M = (mm < 3)
                ? A  + (size_t)mm      * (size_t)NN * (size_t)NN
                : At + (size_t)(mm - 3) * (size_t)NN * (size_t)NN;
            const int slot = (2 * step + h) % NSLOT;
            const uint32_t mb = mbar0 + 8u * (uint32_t)slot;
            const int gi = i0 + HR * h + t;
            const uint32_t sz = (gi < NN) ? row_bytes : 0u;
            mbar_expect_tx(mb, sz);
            if (sz) bulk_g2s(smem_base + (uint32_t)(slot * SLOTF + t * HPD) * 4u,
                             M + (size_t)gi * NN + j0, sz, mb);
        }
    };

    // ---- stage unscaled tf32 S^T tiles for group g ----
    auto stage_S = [&](int g) {
#pragma unroll
        for (int it = 0; it < 8; it++) {
            const int idx = t + NTHREADS * it;    // 0..4095
            const int half = idx >> 11;
            const int n = (idx >> 7) & 15, k = idx & 127;
            const float v = g_St[g][n][(half ? i0 : j0) + k];
            (half ? S2u : S1u)[n * SPD + k] = __uint_as_float(f2tf32(v));
        }
    };

    uint32_t breg[64];
    auto load_B = [&]() {
        const float* __restrict__ Bp = (side ? S2u : S1u) + p * SPD + q;
#pragma unroll
        for (int ks = 0; ks < 16; ks++) {
            const int kb = 8 * ks;
            breg[4 * ks + 0] = __float_as_uint(Bp[kb]);
            breg[4 * ks + 1] = __float_as_uint(Bp[kb + 4]);
            breg[4 * ks + 2] = __float_as_uint(Bp[8 * SPD + kb]);
            breg[4 * ks + 3] = __float_as_uint(Bp[8 * SPD + kb + 4]);
        }
    };

    float acc[8], araw[8];
#pragma unroll
    for (int a = 0; a < 8; a++) { acc[a] = 0.f; araw[a] = 0.f; }

    auto flush = [&](int goff) {
        const int base_row = ((side == 0) ? i0 : j0) + 16 * wsub;
#pragma unroll
        for (int ng = 0; ng < 2; ng++) {
            float* ap = acc + 4 * ng;
            const int col = goff + 8 * ng + 2 * q;
            const int r0 = base_row + p;
            if (r0 < NN)     red_add_v2(out + (size_t)r0 * 32 + col, ap[0], ap[1]);
            if (r0 + 8 < NN) red_add_v2(out + (size_t)(r0 + 8) * 32 + col, ap[2], ap[3]);
        }
#pragma unroll
        for (int a = 0; a < 8; a++) acc[a] = 0.f;
    };

    // ---- two matrices (4 halves) in flight + group-0 S staged, B in regs ----
    issue_half(0, 0); issue_half(0, 1);
    issue_half(1, 0); issue_half(1, 1);
    stage_S(0);
    __syncthreads();
    load_B();

    for (int step = 0; step < NMAT; step++) {
        const int mm = matid(step);
        const float w = (mm < 3) ? wA[mm] : wB[mm - 3];

#pragma unroll
        for (int h = 0; h < 2; h++) {
            const int ph = 2 * step + h;
            const int slot = ph % NSLOT;
            const uint32_t parity = (uint32_t)((ph / NSLOT) & 1);
            const float* __restrict__ Tb = smem + slot * SLOTF;

            if (side == 0) {
                if (h == myhalf) {
                    mbar_wait(mbar0 + 8u * (uint32_t)slot, parity);
                    // rows 16*(wsub&3).. within my half; full K = 128 cols
                    const float* __restrict__ Ta = Tb + (16 * (wsub & 3) + p) * HPD + q;
#pragma unroll
                    for (int ks = 0; ks < 16; ks++) {
                        const int kb = 8 * ks;
                        const uint32_t a0 = __float_as_uint(Ta[kb]);
                        const uint32_t a1 = __float_as_uint(Ta[8 * HPD + kb]);
                        const uint32_t a2 = __float_as_uint(Ta[kb + 4]);
                        const uint32_t a3 = __float_as_uint(Ta[8 * HPD + kb + 4]);
                        mma_tf32(araw,     a0, a1, a2, a3, breg[4 * ks + 0], breg[4 * ks + 1]);
                        mma_tf32(araw + 4, a0, a1, a2, a3, breg[4 * ks + 2], breg[4 * ks + 3]);
                    }
                }
            } else {
                mbar_wait(mbar0 + 8u * (uint32_t)slot, parity);
                // out rows j0+16wsub..+16; K-range 64h..64h+63 (local rows of half)
                const float* __restrict__ Tt = Tb + 16 * wsub + p;
#pragma unroll
                for (int ks = 0; ks < 8; ks++) {
                    const int kb = 8 * ks;
                    const int kg = 4 * (8 * h + ks);
                    const float* __restrict__ Tc = Tt + (kb + q) * HPD;
                    const uint32_t a0 = __float_as_uint(Tc[0]);
                    const uint32_t a1 = __float_as_uint(Tc[8]);
                    const uint32_t a2 = __float_as_uint(Tc[4 * HPD]);
                    const uint32_t a3 = __float_as_uint(Tc[4 * HPD + 8]);
                    mma_tf32(araw,     a0, a1, a2, a3, breg[kg + 0], breg[kg + 1]);
                    mma_tf32(araw + 4, a0, a1, a2, a3, breg[kg + 2], breg[kg + 3]);
                }
            }
        }

        // fold matrix weight into the running group accumulator
#pragma unroll
        for (int a = 0; a < 8; a++) { acc[a] = fmaf(w, araw[a], acc[a]); araw[a] = 0.f; }

        if (step == 2) flush(0);          // group A -> cols 0..15
        if (step == NMAT - 1) flush(16);  // group B -> cols 16..31

        __syncthreads();   // all warps done with step -> slots of step-1 reusable

        if (step + 2 < NMAT) {
            issue_half(step + 2, 0);
            issue_half(step + 2, 1);
        }
        if (step == 2) {   // group switch: restage S for group B
            stage_S(1);
            __syncthreads();
            load_B();
        }
    }
}

extern "C" void kernel_launch(void* const* d_in, const int* in_sizes, int n_in,
                              void* d_out, int out_size) {
    const float* feature = (const float*)d_in[0];  // [5000,128]
    const float* A       = (const float*)d_in[1];  // [3,5000,5000]
    const float* At      = (const float*)d_in[2];  // [9,5000,5000]
    const float* wb2     = (const float*)d_in[3];  // [3,1]
    const float* wb      = (const float*)d_in[4];  // [9,1]
    const float* W3      = (const float*)d_in[5];  // [128,16]
    const float* b3      = (const float*)d_in[6];  // [16]
    const float* W1      = (const float*)d_in[7];  // [128,16]
    const float* b1      = (const float*)d_in[8];  // [16]
    float* out = (float*)d_out;                    // [5000,32]

    fame_prep<<<NN, 128>>>(feature, W3, b3, W1, b1, out);

    // 6 half-slots + 2 S tiles + 6 mbarriers (48 B)
    const int smem_bytes = (NSLOT * SLOTF + 2 * 16 * SPD) * (int)sizeof(float) + 48;
    cudaFuncSetAttribute(fame_main, cudaFuncAttributeMaxDynamicSharedMemorySize, smem_bytes);
    dim3 grid((NN + BT - 1) / BT, (NN + BT - 1) / BT);
    fame_main<<<grid, NTHREADS, smem_bytes>>>(A, At, wb2, wb, out);
}

// round 14
// speedup vs baseline: 1.2864x; 1.2864x over previous
#include <cuda_runtime.h>
#include <cstdint>

#define NN 5000
#define BT 128
#define NTB 40           // tiles per dimension
#define NT (NTB * NTB)   // 1600 tiles
#define TPD 132          // T row stride (floats), 16B-aligned, conflict-free
#define SPD 132          // S row stride
#define NPAD 5120
#define NTHREADS 512
#define NMAT 12
#define SLOT (BT * TPD)  // floats per tile slot
#define ROWB 512u        // bytes per staged tile row (128 f32)

__device__ float g_St[2][16][NPAD];           // transposed supports; pad rows zero
__device__ __align__(16) float g_zero[128];   // zero source for edge rows/tails

// ---------------- helpers ----------------
__device__ __forceinline__ uint32_t f2tf32(float x) {
    uint32_t r;
    asm("cvt.rna.tf32.f32 %0, %1;" : "=r"(r) : "f"(x));
    return r;
}
__device__ __forceinline__ void mma_tf32(float* d, uint32_t a0, uint32_t a1,
                                         uint32_t a2, uint32_t a3,
                                         uint32_t b0, uint32_t b1) {
    asm volatile(
        "mma.sync.aligned.m16n8k8.row.col.f32.tf32.tf32.f32 "
        "{%0,%1,%2,%3}, {%4,%5,%6,%7}, {%8,%9}, {%0,%1,%2,%3};"
        : "+f"(d[0]), "+f"(d[1]), "+f"(d[2]), "+f"(d[3])
        : "r"(a0), "r"(a1), "r"(a2), "r"(a3), "r"(b0), "r"(b1));
}
__device__ __forceinline__ void red_add_v2(float* p, float x, float y) {
    asm volatile("red.global.add.v2.f32 [%0], {%1, %2};"
                 :: "l"(p), "f"(x), "f"(y) : "memory");
}
__device__ __forceinline__ void mbar_init(uint32_t mbar, uint32_t cnt) {
    asm volatile("mbarrier.init.shared.b64 [%0], %1;"
                 :: "r"(mbar), "r"(cnt) : "memory");
}
__device__ __forceinline__ void mbar_expect_tx(uint32_t mbar, uint32_t bytes) {
    asm volatile("mbarrier.arrive.expect_tx.shared.b64 _, [%0], %1;"
                 :: "r"(mbar), "r"(bytes) : "memory");
}
__device__ __forceinline__ void bulk_g2s(uint32_t dst, const void* src,
                                         uint32_t bytes, uint32_t mbar) {
    asm volatile(
        "cp.async.bulk.shared::cta.global.mbarrier::complete_tx::bytes "
        "[%0], [%1], %2, [%3];"
        :: "r"(dst), "l"(src), "r"(bytes), "r"(mbar) : "memory");
}
__device__ __forceinline__ void mbar_wait(uint32_t mbar, uint32_t parity) {
    uint32_t done;
    asm volatile(
        "{\n\t.reg .pred p;\n\t"
        "mbarrier.try_wait.parity.acquire.cta.shared::cta.b64 p, [%1], %2;\n\t"
        "selp.b32 %0, 1, 0, p;\n\t}"
        : "=r"(done) : "r"(mbar), "r"(parity) : "memory");
    if (!done) {
        asm volatile(
            "{\n\t.reg .pred P1;\n\t"
            "WAIT_LOOP_%=:\n\t"
            "mbarrier.try_wait.parity.acquire.cta.shared::cta.b64 P1, [%0], %1, 0x989680;\n\t"
            "@P1 bra.uni WAIT_DONE_%=;\n\t"
            "bra.uni WAIT_LOOP_%=;\n\t"
            "WAIT_DONE_%=:\n\t}"
            :: "r"(mbar), "r"(parity) : "memory");
    }
}

// ---------------- prep: g_St = (feature @ W)^T, bias-init out ----------------
__global__ void fame_prep(const float* __restrict__ feature,
                          const float* __restrict__ W3, const float* __restrict__ b3,
                          const float* __restrict__ W1, const float* __restrict__ b1,
                          float* __restrict__ out) {
    __shared__ float fsm[128];
    const int row = blockIdx.x;
    const int t = threadIdx.x;
    fsm[t] = feature[row * 128 + t];
    __syncthreads();
    if (t < 32) {
        const int g = t >> 4;
        const int c = t & 15;
        const float* __restrict__ W = g ? W1 : W3;
        float s = 0.f;
#pragma unroll 16
        for (int k = 0; k < 128; k++) s += fsm[k] * W[k * 16 + c];
        g_St[g][c][row] = s;
    } else if (t < 64) {
        const int c = t - 32;
        out[row * 32 + c] = (c < 16) ? b3[c] : b1[c - 16];
    }
}

// -- main: persistent CTAs, continuous 3-slot bulk ring, reg-B TF32 mma --
__global__ __launch_bounds__(NTHREADS, 1)
void fame_main(const float* __restrict__ A, const float* __restrict__ At,
               const float* __restrict__ wA, const float* __restrict__ wB,
               float* __restrict__ out)
{
    extern __shared__ float smem[];
    float* S1u = smem + 3 * SLOT;            // [16][132] tf32 S^T rows j0..
    float* S2u = S1u + 16 * SPD;             // [16][132] tf32 S^T rows i0..
    const uint32_t smem_base = (uint32_t)__cvta_generic_to_shared(smem);
    const uint32_t mbar0 = smem_base + (uint32_t)(3 * SLOT + 2 * 16 * SPD) * 4u;

    const int t = threadIdx.x;
    const int wid = t >> 5, lane = t & 31;
    const int p = lane >> 2, q = lane & 3;
    const int side = wid >> 3;               // 0: direct GEMM, 1: transpose GEMM
    const int wsub = wid & 7;                // 16-row slice within side
    const int cta = blockIdx.x;
    const int G = gridDim.x;

    int nt = 0;
    for (int tt = cta; tt < NT; tt += G) nt++;
    if (nt == 0) return;
    const int total = nt * NMAT;

    if (t < 3) mbar_init(mbar0 + 8u * (uint32_t)t, 128u);
    __syncthreads();

    // ---- bulk-copy the tile of global step s into slot s%3 ----
    auto issue_step = [&](int s) {
        if (t < 128) {
            const int tt = cta + (s / NMAT) * G;
            const int ti0 = (tt / NTB) * BT, tj0 = (tt % NTB) * BT;
            const int m = s % NMAT;
            const float* __restrict__ M = (m < 3)
                ? A  + (size_t)m       * (size_t)NN * (size_t)NN
                : At + (size_t)(m - 3) * (size_t)NN * (size_t)NN;
            const int slot = s % 3;
            const uint32_t mb = mbar0 + 8u * (uint32_t)slot;
            const uint32_t dst = smem_base + (uint32_t)(slot * SLOT + t * TPD) * 4u;
            const int gi = ti0 + t;
            mbar_expect_tx(mb, ROWB);
            if (gi < NN) {
                const uint32_t rb = (uint32_t)((tj0 + BT <= NN) ? (int)ROWB
                                                                : (NN - tj0) * 4);
                bulk_g2s(dst, M + (size_t)gi * NN + tj0, rb, mb);
                if (rb < ROWB) bulk_g2s(dst + rb, g_zero, ROWB - rb, mb);
            } else {
                bulk_g2s(dst, g_zero, ROWB, mb);
            }
        }
    };

    // ---- stage unscaled tf32 S^T tiles for group g of tile (ti0, tj0) ----
    auto stage_S = [&](int g, int ti0, int tj0) {
#pragma unroll
        for (int it = 0; it < 8; it++) {
            const int idx = t + NTHREADS * it;    // 0..4095
            const int half = idx >> 11;
            const int n = (idx >> 7) & 15, k = idx & 127;
            const float v = g_St[g][n][(half ? ti0 : tj0) + k];
            (half ? S2u : S1u)[n * SPD + k] = __uint_as_float(f2tf32(v));
        }
    };

    uint32_t breg[64];
    auto load_B = [&]() {
        const float* __restrict__ Bp = (side ? S2u : S1u) + p * SPD + q;
#pragma unroll
        for (int ks = 0; ks < 16; ks++) {
            const int kb = 8 * ks;
            breg[4 * ks + 0] = __float_as_uint(Bp[kb]);
            breg[4 * ks + 1] = __float_as_uint(Bp[kb + 4]);
            breg[4 * ks + 2] = __float_as_uint(Bp[8 * SPD + kb]);
            breg[4 * ks + 3] = __float_as_uint(Bp[8 * SPD + kb + 4]);
        }
    };

    float acc[8], araw[8];
#pragma unroll
    for (int a = 0; a < 8; a++) { acc[a] = 0.f; araw[a] = 0.f; }

    auto flush = [&](int goff, int ti0, int tj0) {
        const int base_row = ((side == 0) ? ti0 : tj0) + 16 * wsub;
#pragma unroll
        for (int ng = 0; ng < 2; ng++) {
            float* ap = acc + 4 * ng;
            const int col = goff + 8 * ng + 2 * q;
            const int r0 = base_row + p;
            if (r0 < NN)     red_add_v2(out + (size_t)r0 * 32 + col, ap[0], ap[1]);
            if (r0 + 8 < NN) red_add_v2(out + (size_t)(r0 + 8) * 32 + col, ap[2], ap[3]);
        }
#pragma unroll
        for (int a = 0; a < 8; a++) acc[a] = 0.f;
    };

    // ---- prologue: fill pipeline once per CTA lifetime ----
    int cur = cta;
    int i0 = (cur / NTB) * BT, j0 = (cur % NTB) * BT;
    issue_step(0);
    if (total > 1) issue_step(1);
    stage_S(0, i0, j0);
    __syncthreads();
    load_B();

    for (int s = 0; s < total; s++) {
        const int m = s % NMAT;
        const int slot = s % 3;
        mbar_wait(mbar0 + 8u * (uint32_t)slot, (uint32_t)((s / 3) & 1));
        __syncthreads();   // + all warps finished compute on step s-1 (slot reuse safe)

        if (s + 2 < total) issue_step(s + 2);

        if (m == 3) {      // group switch: restage S (group-A compute all done)
            stage_S(1, i0, j0);
            __syncthreads();
            load_B();
        }

        const float* __restrict__ Tb = smem + slot * SLOT;
        const float w = (m < 3) ? wA[m] : wB[m - 3];

        if (side == 0) {
            const float* __restrict__ Ta = Tb + (16 * wsub + p) * TPD + q;
#pragma unroll
            for (int ks = 0; ks < 16; ks++) {
                const int kb = 8 * ks;
                const uint32_t a0 = __float_as_uint(Ta[kb]);           // HW f32->tf32 truncation
                const uint32_t a1 = __float_as_uint(Ta[8 * TPD + kb]);
                const uint32_t a2 = __float_as_uint(Ta[kb + 4]);
                const uint32_t a3 = __float_as_uint(Ta[8 * TPD + kb + 4]);
                mma_tf32(araw,     a0, a1, a2, a3, breg[4 * ks + 0], breg[4 * ks + 1]);
                mma_tf32(araw + 4, a0, a1, a2, a3, breg[4 * ks + 2], breg[4 * ks + 3]);
            }
        } else {
            const float* __restrict__ Tt = Tb + 16 * wsub + p;
#pragma unroll
            for (int ks = 0; ks < 16; ks++) {
                const int kb = 8 * ks;
                const float* __restrict__ Tc = Tt + (kb + q) * TPD;
                const uint32_t a0 = __float_as_uint(Tc[0]);
                const uint32_t a1 = __float_as_uint(Tc[8]);
                const uint32_t a2 = __float_as_uint(Tc[4 * TPD]);
                const uint32_t a3 = __float_as_uint(Tc[4 * TPD + 8]);
                mma_tf32(araw,     a0, a1, a2, a3, breg[4 * ks + 0], breg[4 * ks + 1]);
                mma_tf32(araw + 4, a0, a1, a2, a3, breg[4 * ks + 2], breg[4 * ks + 3]);
            }
        }

        // fold matrix weight into the running group accumulator
#pragma unroll
        for (int a = 0; a < 8; a++) { acc[a] = fmaf(w, araw[a], acc[a]); araw[a] = 0.f; }

        if (m == 2) flush(0, i0, j0);          // group A -> cols 0..15
        if (m == NMAT - 1) {
            flush(16, i0, j0);                 // group B -> cols 16..31
            if (s + 1 < total) {               // advance to next tile; restage S(g0)
                cur += G;
                i0 = (cur / NTB) * BT;
                j0 = (cur % NTB) * BT;
                stage_S(0, i0, j0);
                __syncthreads();
                load_B();
            }
        }
    }
}

extern "C" void kernel_launch(void* const* d_in, const int* in_sizes, int n_in,
                              void* d_out, int out_size) {
    const float* feature = (const float*)d_in[0];  // [5000,128]
    const float* A       = (const float*)d_in[1];  // [3,5000,5000]
    const float* At      = (const float*)d_in[2];  // [9,5000,5000]
    const float* wb2     = (const float*)d_in[3];  // [3,1]
    const float* wb      = (const float*)d_in[4];  // [9,1]
    const float* W3      = (const float*)d_in[5];  // [128,16]
    const float* b3      = (const float*)d_in[6];  // [16]
    const float* W1      = (const float*)d_in[7];  // [128,16]
    const float* b1      = (const float*)d_in[8];  // [16]
    float* out = (float*)d_out;                    // [5000,32]

    fame_prep<<<NN, 128>>>(feature, W3, b3, W1, b1, out);

    int sms = 148;
    cudaDeviceGetAttribute(&sms, cudaDevAttrMultiProcessorCount, 0);
    if (sms < 1) sms = 148;

    // 3 slots + 2 S tiles + 3 mbarriers (24 B)
    const int smem_bytes = (3 * SLOT + 2 * 16 * SPD) * (int)sizeof(float) + 24;
    cudaFuncSetAttribute(fame_main, cudaFuncAttributeMaxDynamicSharedMemorySize, smem_bytes);
    fame_main<<<sms, NTHREADS, smem_bytes>>>(A, At, wb2, wb, out);
}

// round 15
// speedup vs baseline: 1.6725x; 1.3001x over previous
#include <cuda_runtime.h>
#include <cuda.h>
#include <cstdint>
#include <cstring>

#define NN 5000
#define BT 128
#define SPD 132          // S row stride (floats)
#define NPAD 5120
#define NTHREADS 512
#define NMAT 12
#define SLOTB 65536u     // bytes per dense SW128 tile slot (128x128 f32)
#define SFL 49152        // float offset of S region (after 3 slots)

struct TMaps { CUtensorMap m[NMAT]; };

__device__ float g_St[2][16][NPAD];   // transposed supports; pad rows zero

// ---------------- helpers ----------------
__device__ __forceinline__ uint32_t f2tf32(float x) {
    uint32_t r;
    asm("cvt.rna.tf32.f32 %0, %1;" : "=r"(r) : "f"(x));
    return r;
}
__device__ __forceinline__ void mma_tf32(float* d, uint32_t a0, uint32_t a1,
                                         uint32_t a2, uint32_t a3,
                                         uint32_t b0, uint32_t b1) {
    asm volatile(
        "mma.sync.aligned.m16n8k8.row.col.f32.tf32.tf32.f32 "
        "{%0,%1,%2,%3}, {%4,%5,%6,%7}, {%8,%9}, {%0,%1,%2,%3};"
        : "+f"(d[0]), "+f"(d[1]), "+f"(d[2]), "+f"(d[3])
        : "r"(a0), "r"(a1), "r"(a2), "r"(a3), "r"(b0), "r"(b1));
}
__device__ __forceinline__ void red_add_v2(float* p, float x, float y) {
    asm volatile("red.global.add.v2.f32 [%0], {%1, %2};"
                 :: "l"(p), "f"(x), "f"(y) : "memory");
}
__device__ __forceinline__ void mbar_init(uint32_t mbar, uint32_t cnt) {
    asm volatile("mbarrier.init.shared.b64 [%0], %1;"
                 :: "r"(mbar), "r"(cnt) : "memory");
}
__device__ __forceinline__ void mbar_expect_tx(uint32_t mbar, uint32_t bytes) {
    asm volatile("mbarrier.arrive.expect_tx.shared.b64 _, [%0], %1;"
                 :: "r"(mbar), "r"(bytes) : "memory");
}
__device__ __forceinline__ void tma2d(uint32_t dst, const void* map,
                                      int x, int y, uint32_t mbar) {
    asm volatile(
        "cp.async.bulk.tensor.2d.shared::cta.global.tile.mbarrier::complete_tx::bytes "
        "[%0], [%1, {%2, %3}], [%4];"
        :: "r"(dst), "l"(map), "r"(x), "r"(y), "r"(mbar) : "memory");
}
__device__ __forceinline__ void mbar_wait(uint32_t mbar, uint32_t parity) {
    uint32_t done;
    asm volatile(
        "{\n\t.reg .pred p;\n\t"
        "mbarrier.try_wait.parity.acquire.cta.shared::cta.b64 p, [%1], %2;\n\t"
        "selp.b32 %0, 1, 0, p;\n\t}"
        : "=r"(done) : "r"(mbar), "r"(parity) : "memory");
    if (!done) {
        asm volatile(
            "{\n\t.reg .pred P1;\n\t"
            "WAIT_LOOP_%=:\n\t"
            "mbarrier.try_wait.parity.acquire.cta.shared::cta.b64 P1, [%0], %1, 0x989680;\n\t"
            "@P1 bra.uni WAIT_DONE_%=;\n\t"
            "bra.uni WAIT_LOOP_%=;\n\t"
            "WAIT_DONE_%=:\n\t}"
            :: "r"(mbar), "r"(parity) : "memory");
    }
}

// ---------------- prep: g_St = (feature @ W)^T, bias-init out ----------------
__global__ void fame_prep(const float* __restrict__ feature,
                          const float* __restrict__ W3, const float* __restrict__ b3,
                          const float* __restrict__ W1, const float* __restrict__ b1,
                          float* __restrict__ out) {
    __shared__ float fsm[128];
    const int row = blockIdx.x;
    const int t = threadIdx.x;
    fsm[t] = feature[row * 128 + t];
    __syncthreads();
    if (t < 32) {
        const int g = t >> 4;
        const int c = t & 15;
        const float* __restrict__ W = g ? W1 : W3;
        float s = 0.f;
#pragma unroll 16
        for (int k = 0; k < 128; k++) s += fsm[k] * W[k * 16 + c];
        g_St[g][c][row] = s;
    } else if (t < 64) {
        const int c = t - 32;
        out[row * 32 + c] = (c < 16) ? b3[c] : b1[c - 16];
    }
}

// ---- main: tensor-map TMA 3-slot ring (4 req/tile), reg-B TF32 mma ----
__global__ __launch_bounds__(NTHREADS, 1)
void fame_main(const __grid_constant__ TMaps maps,
               const float* __restrict__ wA, const float* __restrict__ wB,
               float* __restrict__ out)
{
    extern __shared__ __align__(1024) float smem[];
    float* S1u = smem + SFL;                 // [16][132] tf32 S^T rows j0..
    float* S2u = S1u + 16 * SPD;             // [16][132] tf32 S^T rows i0..
    const uint32_t smem_base = (uint32_t)__cvta_generic_to_shared(smem);
    const uint32_t mbar0 = smem_base + (uint32_t)(SFL + 2 * 16 * SPD) * 4u;

    const int t = threadIdx.x;
    const int wid = t >> 5, lane = t & 31;
    const int p = lane >> 2, q = lane & 3;
    const int side = wid >> 3;               // 0: direct GEMM, 1: transpose GEMM
    const int wsub = wid & 7;                // 16-row slice within side
    const int i0 = blockIdx.y * BT, j0 = blockIdx.x * BT;

    if (t < 3) mbar_init(mbar0 + 8u * (uint32_t)t, 4u);
    __syncthreads();

    // ---- TMA: 4 box loads (32 cols x 128 rows, SW128) per tile ----
    auto issue_tile = [&](int m) {
        if (t < 4) {
            const int slot = m % 3;
            const uint32_t mb = mbar0 + 8u * (uint32_t)slot;
            const uint32_t dst = smem_base + (uint32_t)slot * SLOTB
                               + (uint32_t)t * 16384u;
            mbar_expect_tx(mb, 16384u);
            tma2d(dst, &maps.m[m], j0 + 32 * t, i0, mb);
        }
    };

    // ---- stage unscaled tf32 S^T tiles for group g ----
    auto stage_S = [&](int g) {
#pragma unroll
        for (int it = 0; it < 8; it++) {
            const int idx = t + NTHREADS * it;    // 0..4095
            const int half = idx >> 11;
            const int n = (idx >> 7) & 15, k = idx & 127;
            const float v = g_St[g][n][(half ? i0 : j0) + k];
            (half ? S2u : S1u)[n * SPD + k] = __uint_as_float(f2tf32(v));
        }
    };

    uint32_t breg[64];
    auto load_B = [&]() {
        const float* __restrict__ Bp = (side ? S2u : S1u) + p * SPD + q;
#pragma unroll
        for (int ks = 0; ks < 16; ks++) {
            const int kb = 8 * ks;
            breg[4 * ks + 0] = __float_as_uint(Bp[kb]);
            breg[4 * ks + 1] = __float_as_uint(Bp[kb + 4]);
            breg[4 * ks + 2] = __float_as_uint(Bp[8 * SPD + kb]);
            breg[4 * ks + 3] = __float_as_uint(Bp[8 * SPD + kb + 4]);
        }
    };

    float acc[8], araw[8];
#pragma unroll
    for (int a = 0; a < 8; a++) { acc[a] = 0.f; araw[a] = 0.f; }

    auto flush = [&](int goff) {
        const int base_row = ((side == 0) ? i0 : j0) + 16 * wsub;
#pragma unroll
        for (int ng = 0; ng < 2; ng++) {
            float* ap = acc + 4 * ng;
            const int col = goff + 8 * ng + 2 * q;
            const int r0 = base_row + p;
            if (r0 < NN)     red_add_v2(out + (size_t)r0 * 32 + col, ap[0], ap[1]);
            if (r0 + 8 < NN) red_add_v2(out + (size_t)(r0 + 8) * 32 + col, ap[2], ap[3]);
        }
#pragma unroll
        for (int a = 0; a < 8; a++) acc[a] = 0.f;
    };

    // precomputed SW128 addressing constants
    // side0: element (r, col): byte = chunk(col>>5)*16384 + r*128 + (((col&31)*4) ^ ((r&7)<<4))
    const uint32_t s0_base = (uint32_t)((16 * wsub + p) * 128);
    const uint32_t s0_rxor = (uint32_t)(p << 4);
    const uint32_t s0_q4 = (uint32_t)(4 * q);
    // side1: col c1(+8) fixed per thread, rows 8ks+q (+4): row&7 = q (q+4), fixed
    const uint32_t s1_chunk = (uint32_t)((wsub >> 1) * 16384);
    const uint32_t s1_c4 = (uint32_t)((16 * (wsub & 1) + p) * 4);
    const uint32_t s1_o0 = s1_chunk + (uint32_t)(q * 128) + (s1_c4 ^ (uint32_t)(q << 4));
    const uint32_t s1_o1 = s1_chunk + (uint32_t)(q * 128) + ((s1_c4 + 32u) ^ (uint32_t)(q << 4));
    const uint32_t s1_o2 = s1_chunk + (uint32_t)((q + 4) * 128) + (s1_c4 ^ (uint32_t)((q + 4) << 4));
    const uint32_t s1_o3 = s1_chunk + (uint32_t)((q + 4) * 128) + ((s1_c4 + 32u) ^ (uint32_t)((q + 4) << 4));

    // ---- two tiles in flight + group-0 S staged, B in regs ----
    issue_tile(0);
    issue_tile(1);
    stage_S(0);
    __syncthreads();
    load_B();

    for (int m = 0; m < NMAT; m++) {
        const int slot = m % 3;
        mbar_wait(mbar0 + 8u * (uint32_t)slot, (uint32_t)((m / 3) & 1));
        __syncthreads();   // + all warps finished compute on tile m-1 (slot reuse safe)

        if (m + 2 < NMAT) issue_tile(m + 2);

        if (m == 3) {      // group switch: restage S (group-A compute all done)
            stage_S(1);
            __syncthreads();
            load_B();
        }

        const char* __restrict__ Tb = (const char*)smem + (uint32_t)slot * SLOTB;
        const float w = (m < 3) ? wA[m] : wB[m - 3];

        if (side == 0) {
#pragma unroll
            for (int ks = 0; ks < 16; ks++) {
                const uint32_t chunk = (uint32_t)((ks >> 2) * 16384);
                const uint32_t cb0 = (uint32_t)((ks & 3) * 32) + s0_q4;
                const uint32_t off0 = chunk + s0_base + (cb0 ^ s0_rxor);
                const uint32_t off2 = chunk + s0_base + ((cb0 + 16u) ^ s0_rxor);
                const uint32_t a0 = __float_as_uint(*(const float*)(Tb + off0));
                const uint32_t a1 = __float_as_uint(*(const float*)(Tb + off0 + 1024));
                const uint32_t a2 = __float_as_uint(*(const float*)(Tb + off2));
                const uint32_t a3 = __float_as_uint(*(const float*)(Tb + off2 + 1024));
                mma_tf32(araw,     a0, a1, a2, a3, breg[4 * ks + 0], breg[4 * ks + 1]);
                mma_tf32(araw + 4, a0, a1, a2, a3, breg[4 * ks + 2], breg[4 * ks + 3]);
            }
        } else {
#pragma unroll
            for (int ks = 0; ks < 16; ks++) {
                const uint32_t rb = (uint32_t)(ks * 1024);
                const uint32_t a0 = __float_as_uint(*(const float*)(Tb + s1_o0 + rb));
                const uint32_t a1 = __float_as_uint(*(const float*)(Tb + s1_o1 + rb));
                const uint32_t a2 = __float_as_uint(*(const float*)(Tb + s1_o2 + rb));
                const uint32_t a3 = __float_as_uint(*(const float*)(Tb + s1_o3 + rb));
                mma_tf32(araw,     a0, a1, a2, a3, breg[4 * ks + 0], breg[4 * ks + 1]);
                mma_tf32(araw + 4, a0, a1, a2, a3, breg[4 * ks + 2], breg[4 * ks + 3]);
            }
        }

        // fold matrix weight into the running group accumulator
#pragma unroll
        for (int a = 0; a < 8; a++) { acc[a] = fmaf(w, araw[a], acc[a]); araw[a] = 0.f; }

        if (m == 2) flush(0);          // group A -> cols 0..15
        if (m == NMAT - 1) flush(16);  // group B -> cols 16..31
    }
}

// ---------------- host ----------------
typedef CUresult (*PFN_tmapEncode)(
    CUtensorMap*, CUtensorMapDataType, cuuint32_t, void*,
    const cuuint64_t*, const cuuint64_t*, const cuuint32_t*, const cuuint32_t*,
    CUtensorMapInterleave, CUtensorMapSwizzle, CUtensorMapL2promotion,
    CUtensorMapFloatOOBfill);

extern "C" void kernel_launch(void* const* d_in, const int* in_sizes, int n_in,
                              void* d_out, int out_size) {
    const float* feature = (const float*)d_in[0];  // [5000,128]
    const float* A       = (const float*)d_in[1];  // [3,5000,5000]
    const float* At      = (const float*)d_in[2];  // [9,5000,5000]
    const float* wb2     = (const float*)d_in[3];  // [3,1]
    const float* wb      = (const float*)d_in[4];  // [9,1]
    const float* W3      = (const float*)d_in[5];  // [128,16]
    const float* b3      = (const float*)d_in[6];  // [16]
    const float* W1      = (const float*)d_in[7];  // [128,16]
    const float* b1      = (const float*)d_in[8];  // [16]
    float* out = (float*)d_out;                    // [5000,32]

    fame_prep<<<NN, 128>>>(feature, W3, b3, W1, b1, out);

    // encode 12 tensor maps (driver entry point; no -lcuda link needed)
    static PFN_tmapEncode pfn = nullptr;
    if (!pfn) {
        cudaDriverEntryPointQueryResult qres;
        void* fp = nullptr;
        cudaGetDriverEntryPointByVersion("cuTensorMapEncodeTiled", &fp, 12000,
                                         cudaEnableDefault, &qres);
        pfn = (PFN_tmapEncode)fp;
    }
    TMaps maps;
    const cuuint64_t gdim[2] = {(cuuint64_t)NN, (cuuint64_t)NN};
    const cuuint64_t gstr[1] = {(cuuint64_t)NN * 4};
    const cuuint32_t box[2] = {32u, 128u};
    const cuuint32_t estr[2] = {1u, 1u};
    for (int m = 0; m < NMAT; m++) {
        void* base = (void*)((m < 3)
            ? A  + (size_t)m       * (size_t)NN * (size_t)NN
            : At + (size_t)(m - 3) * (size_t)NN * (size_t)NN);
        pfn(&maps.m[m], CU_TENSOR_MAP_DATA_TYPE_FLOAT32, 2, base,
            gdim, gstr, box, estr,
            CU_TENSOR_MAP_INTERLEAVE_NONE, CU_TENSOR_MAP_SWIZZLE_128B,
            CU_TENSOR_MAP_L2_PROMOTION_L2_128B, CU_TENSOR_MAP_FLOAT_OOB_FILL_NONE);
    }

    // 3 dense slots (192KB) + 2 S tiles + 3 mbarriers
    const int smem_bytes = (int)(3 * SLOTB) + 2 * 16 * SPD * (int)sizeof(float) + 24;
    cudaFuncSetAttribute(fame_main, cudaFuncAttributeMaxDynamicSharedMemorySize, smem_bytes);
    dim3 grid((NN + BT - 1) / BT, (NN + BT - 1) / BT);
    fame_main<<<grid, NTHREADS, smem_bytes>>>(maps, wb2, wb, out);
}